// round 10
// baseline (speedup 1.0000x reference)
#include <cuda_runtime.h>
#include <cuda_fp16.h>
#include <cstdint>

// ---------------- problem constants ----------------
#define BATCH 8
#define NHID 256
#define LEN 2048
#define NHEAD 8
#define HDIM 64
#define DQKV 512
#define DOUT 2048
#define MTOT (BATCH * LEN)   // 16384

// ---------------- qkv GEMM tiling (fp16, k-pair packed) ----------------
#define BM 128
#define BN 128
#define BKP 16                // kp rows per chunk (= 32 k elements)
#define PQ 136                // smem pitch in uint32
#define QSZ (BKP * PQ)        // 2176 uint32 per buffer
#define NSTAGE 3
#define SMEM_Q (2 * NSTAGE * QSZ * 4)   // 52224 bytes

// ---------------- out GEMM tiling (64x256, 2-stage, 256 thr) ----------------
#define OM 64
#define ON 256
#define PAO 72                // A pitch (uint32)
#define PBO 264               // B pitch (uint32)
#define AOSZ (BKP * PAO)      // 1152 uint32
#define BOSZ (BKP * PBO)      // 4224 uint32
#define EPPO 68
#define SMEM_O (2 * (AOSZ + BOSZ) * 4)   // 43008 B (>= 34816 epilogue half)

// Scratch (allocation-free). Operands packed as half2 k-pairs: word[kp][col].
__device__ uint32_t g_xh[(size_t)(BATCH * NHID / 2) * LEN];   // [1024][2048]
__device__ uint32_t g_wqh[(NHID / 2) * DQKV];
__device__ uint32_t g_wkh[(NHID / 2) * DQKV];
__device__ uint32_t g_wvh[(NHID / 2) * DQKV];
__device__ uint32_t g_woh[(DQKV / 2) * DOUT];                 // [256][2048]
__device__ uint32_t g_qkvh[(size_t)MTOT * 768];               // fp16 q/k/v, d-pair words
__device__ uint32_t g_atth[(size_t)(DQKV / 2) * MTOT];        // [256][16384]

// ---------------- helpers ----------------
__device__ __forceinline__ uint32_t pkh2(float a, float b) {
    __half2 h = __floats2half2_rn(a, b);
    return *reinterpret_cast<uint32_t*>(&h);
}
__device__ __forceinline__ float2 uph2(uint32_t u) {
    __half2 h;
    *reinterpret_cast<uint32_t*>(&h) = u;
    return __half22float2(h);
}
__device__ __forceinline__ uint32_t smem_u32(const void* p) {
    uint32_t a;
    asm("{ .reg .u64 t; cvta.to.shared.u64 t, %1; cvt.u32.u64 %0, t; }" : "=r"(a) : "l"(p));
    return a;
}
__device__ __forceinline__ void cpa16(uint32_t dst, const void* src) {
    asm volatile("cp.async.cg.shared.global [%0], [%1], 16;" :: "r"(dst), "l"(src));
}
#define CP_COMMIT() asm volatile("cp.async.commit_group;" ::: "memory")
#define CP_WAIT(n)  asm volatile("cp.async.wait_group %0;" :: "n"(n) : "memory")

__device__ __forceinline__ void mma16(float& d0, float& d1, float& d2, float& d3,
                                      uint32_t a0, uint32_t a1, uint32_t a2, uint32_t a3,
                                      uint32_t b0, uint32_t b1) {
    asm volatile(
        "mma.sync.aligned.m16n8k16.row.col.f32.f16.f16.f32 "
        "{%0,%1,%2,%3}, {%4,%5,%6,%7}, {%8,%9}, {%0,%1,%2,%3};"
        : "+f"(d0), "+f"(d1), "+f"(d2), "+f"(d3)
        : "r"(a0), "r"(a1), "r"(a2), "r"(a3), "r"(b0), "r"(b1));
}

// mma over one chunk (16 kp rows = 32 k). Pitches templated.
template <int APITCH, int BPITCH>
__device__ __forceinline__ void mma_chunk(const uint32_t* __restrict__ Ab,
                                          const uint32_t* __restrict__ Bb,
                                          float acc[2][8][4], int mw, int nw,
                                          int c, int g) {
#pragma unroll
    for (int ks = 0; ks < 2; ks++) {
        const int kb = ks * 8;
        uint32_t a[2][4];
#pragma unroll
        for (int fm = 0; fm < 2; fm++) {
            const uint32_t* p = Ab + (kb + c) * APITCH + mw + fm * 16 + g;
            a[fm][0] = p[0];
            a[fm][1] = p[8];
            a[fm][2] = p[4 * APITCH];
            a[fm][3] = p[4 * APITCH + 8];
        }
#pragma unroll
        for (int fn = 0; fn < 8; fn++) {
            const uint32_t* q = Bb + (kb + c) * BPITCH + nw + fn * 8 + g;
            uint32_t b0 = q[0];
            uint32_t b1 = q[4 * BPITCH];
            mma16(acc[0][fn][0], acc[0][fn][1], acc[0][fn][2], acc[0][fn][3],
                  a[0][0], a[0][1], a[0][2], a[0][3], b0, b1);
            mma16(acc[1][fn][0], acc[1][fn][1], acc[1][fn][2], acc[1][fn][3],
                  a[1][0], a[1][1], a[1][2], a[1][3], b0, b1);
        }
    }
}

// ---------------- prep: pack fp32 [K][N] -> half2-k-pair words [K/2][N] ----------------
__device__ __forceinline__ void pack_item(const float* __restrict__ src,
                                          uint32_t* __restrict__ dst,
                                          int cols, int i) {
    int kp = i / (cols / 4);
    int c4 = (i % (cols / 4)) * 4;
    const float4 r0 = *(const float4*)(src + (size_t)(2 * kp) * cols + c4);
    const float4 r1 = *(const float4*)(src + (size_t)(2 * kp + 1) * cols + c4);
    uint4 o;
    o.x = pkh2(r0.x, r1.x);
    o.y = pkh2(r0.y, r1.y);
    o.z = pkh2(r0.z, r1.z);
    o.w = pkh2(r0.w, r1.w);
    *(uint4*)(dst + (size_t)kp * cols + c4) = o;
}

#define NXI ((BATCH * NHID / 2) * (LEN / 4))   // 524288
#define NWI ((NHID / 2) * (DQKV / 4))          // 16384
#define NOI ((DQKV / 2) * (DOUT / 4))          // 131072
#define NTI (NXI + 3 * NWI + NOI)              // 704512

__global__ __launch_bounds__(256) void pack_all(
    const float* __restrict__ x,  const float* __restrict__ wq,
    const float* __restrict__ wk, const float* __restrict__ wv,
    const float* __restrict__ wo)
{
    int i = blockIdx.x * 256 + threadIdx.x;
    if (i >= NTI) return;
    if (i < NXI)                { pack_item(x,  g_xh,  LEN,  i); }
    else if (i < NXI + NWI)     { pack_item(wq, g_wqh, DQKV, i - NXI); }
    else if (i < NXI + 2 * NWI) { pack_item(wk, g_wkh, DQKV, i - NXI - NWI); }
    else if (i < NXI + 3 * NWI) { pack_item(wv, g_wvh, DQKV, i - NXI - 2 * NWI); }
    else                        { pack_item(wo, g_woh, DOUT, i - NXI - 3 * NWI); }
}

// ---------------- Kernel 1: QKV projection (fp16 mma, fp16 packed output) ----------------
__global__ __launch_bounds__(256, 2) void qkv_mma(
    const float* __restrict__ bq, const float* __restrict__ bk,
    const float* __restrict__ bv)
{
    extern __shared__ uint32_t sm[];
    const int tid = threadIdx.x, lane = tid & 31, wid = tid >> 5;
    const int c = lane & 3, g = lane >> 2;
    const int mw = (wid & 3) * 32, nw = (wid >> 2) * 64;

    const int m0 = blockIdx.x * BM;
    const int bb = m0 >> 11;
    const int l0 = m0 & (LEN - 1);
    const int yy = blockIdx.y;               // 0..11
    const int mat = yy >> 2;
    const int n0 = (yy & 3) * BN;

    const uint32_t* W = (mat == 0) ? g_wqh : (mat == 1) ? g_wkh : g_wvh;
    const float* bias = (mat == 0) ? bq : (mat == 1) ? bk : bv;

    const int fkp0 = tid >> 5;
    const uint32_t sbase = smem_u32(sm);
    uint32_t aAddr[NSTAGE], bAddr[NSTAGE];
#pragma unroll
    for (int i = 0; i < NSTAGE; i++) {
        aAddr[i] = sbase + i * QSZ * 4;
        bAddr[i] = sbase + (NSTAGE + i) * QSZ * 4;
    }
    const int m4s = (tid & 31) * 4;
    const uint32_t sdst = (uint32_t)(fkp0 * PQ + m4s) * 4;
    const uint32_t* aS = g_xh + ((size_t)bb * 128 + fkp0) * LEN + l0 + m4s;
    const uint32_t* bS = W + (size_t)fkp0 * DQKV + n0 + m4s;

#define Q_ISSUE(buf, k0p)                                                     \
    {                                                                         \
        _Pragma("unroll") for (int j = 0; j < 2; j++) {                       \
            cpa16(aAddr[buf] + sdst + j * (8 * PQ * 4),                       \
                  aS + (size_t)((k0p) + 8 * j) * LEN);                        \
            cpa16(bAddr[buf] + sdst + j * (8 * PQ * 4),                       \
                  bS + (size_t)((k0p) + 8 * j) * DQKV);                       \
        }                                                                     \
        CP_COMMIT();                                                          \
    }

    float acc[2][8][4];
#pragma unroll
    for (int i = 0; i < 2; i++)
#pragma unroll
        for (int j = 0; j < 8; j++)
#pragma unroll
            for (int r = 0; r < 4; r++) acc[i][j][r] = 0.f;

    const int NCH = (NHID / 2) / BKP;   // 8 chunks
    Q_ISSUE(0, 0);
    Q_ISSUE(1, BKP);
    for (int cc = 0; cc < NCH; cc++) {
        const int cur = cc % NSTAGE;
        if (cc == NCH - 1) { CP_WAIT(0); } else { CP_WAIT(1); }
        __syncthreads();
        if (cc + 2 < NCH) Q_ISSUE((cc + 2) % NSTAGE, (cc + 2) * BKP);
        mma_chunk<PQ, PQ>(sm + cur * QSZ, sm + (NSTAGE + cur) * QSZ,
                          acc, mw, nw, c, g);
    }
#undef Q_ISSUE

    // Epilogue: bias + pack to fp16 d-pair words -> g_qkvh
#pragma unroll
    for (int fm = 0; fm < 2; fm++)
#pragma unroll
        for (int fn = 0; fn < 8; fn++) {
            int m = m0 + mw + fm * 16 + g;
            int n = nw + fn * 8 + c * 2;
            float bx = __ldg(bias + n0 + n), by = __ldg(bias + n0 + n + 1);
            uint32_t* p = g_qkvh + (size_t)m * 768 + mat * 256 + ((n0 + n) >> 1);
            p[0]               = pkh2(acc[fm][fn][0] + bx, acc[fm][fn][1] + by);
            p[(size_t)8 * 768] = pkh2(acc[fm][fn][2] + bx, acc[fm][fn][3] + by);
        }
}

// ---------------- Kernel 2: window-3 attention (fp16 in, fp16 packed out) ----------------
__global__ __launch_bounds__(256) void attn_t()
{
    __shared__ float att_s[32 * 66];   // [li][d] pitch 66
    const int tid = threadIdx.x, warp = tid >> 5, lane = tid & 31;
    const int bid = blockIdx.x;
    const int b = bid >> 9;
    const int head = (bid >> 6) & 7;
    const int l0 = (bid & 63) * 32;

#pragma unroll
    for (int i = 0; i < 4; i++) {
        const int li = warp * 4 + i;
        const int l = l0 + li;
        const size_t mrow = (size_t)b * LEN + l;
        const uint32_t* base = g_qkvh + mrow * 768 + head * 32 + lane;
        const float2 qv = uph2(base[0]);

        float  s[3];
        float2 vv[3];
#pragma unroll
        for (int w = 0; w < 3; w++) {
            int lw = l + w - 1;
            bool ok = (unsigned)lw < (unsigned)LEN;
            float2 kv = make_float2(0.f, 0.f);
            vv[w] = make_float2(0.f, 0.f);
            if (ok) {
                const uint32_t* pw = base + (intptr_t)(w - 1) * 768;
                kv    = uph2(pw[256]);
                vv[w] = uph2(pw[512]);
            }
            float p = qv.x * kv.x + qv.y * kv.y;
            p += __shfl_xor_sync(0xffffffffu, p, 16);
            p += __shfl_xor_sync(0xffffffffu, p, 8);
            p += __shfl_xor_sync(0xffffffffu, p, 4);
            p += __shfl_xor_sync(0xffffffffu, p, 2);
            p += __shfl_xor_sync(0xffffffffu, p, 1);
            s[w] = p * 0.125f;
        }

        float mx = fmaxf(s[0], fmaxf(s[1], s[2]));
        float e0 = expf(s[0] - mx), e1 = expf(s[1] - mx), e2 = expf(s[2] - mx);
        float inv = 1.0f / (e0 + e1 + e2);
        float ax = (e0 * vv[0].x + e1 * vv[1].x + e2 * vv[2].x) * inv;
        float ay = (e0 * vv[0].y + e1 * vv[1].y + e2 * vv[2].y) * inv;
        *(float2*)&att_s[li * 66 + lane * 2] = make_float2(ax, ay);
    }
    __syncthreads();

    // write g_atth[(head*32+dp)][b*2048 + l0 + l], 4 l's per thread (16B store)
    {
        int dp = tid >> 3;              // 0..31
        int l4 = (tid & 7) * 4;         // 0..28
        uint4 v;
        v.x = pkh2(att_s[(l4 + 0) * 66 + 2 * dp], att_s[(l4 + 0) * 66 + 2 * dp + 1]);
        v.y = pkh2(att_s[(l4 + 1) * 66 + 2 * dp], att_s[(l4 + 1) * 66 + 2 * dp + 1]);
        v.z = pkh2(att_s[(l4 + 2) * 66 + 2 * dp], att_s[(l4 + 2) * 66 + 2 * dp + 1]);
        v.w = pkh2(att_s[(l4 + 3) * 66 + 2 * dp], att_s[(l4 + 3) * 66 + 2 * dp + 1]);
        *(uint4*)(g_atth + (size_t)(head * 32 + dp) * MTOT
                  + (size_t)b * LEN + l0 + l4) = v;
    }
}

// ---------------- Kernel 3: output projection — 64x256 tile, 2-stage, 256 thr ----------------
__global__ __launch_bounds__(256, 2) void out_mma(
    const float* __restrict__ bo, float* __restrict__ out)
{
    extern __shared__ uint32_t sm[];
    // layout: A0, A1 [AOSZ each], B0, B1 [BOSZ each]
    const int tid = threadIdx.x, lane = tid & 31, wid = tid >> 5;
    const int c = lane & 3, g = lane >> 2;
    const int mw = (wid & 1) * 32, nw = (wid >> 1) * 64;   // 2m x 4n warps

    const int m0 = blockIdx.x * OM;
    const int bb = m0 >> 11;
    const int l0 = m0 & (LEN - 1);
    const int n0 = blockIdx.y * ON;

    const uint32_t sbase = smem_u32(sm);
    // A staging: one cpa16 per thread covers 16kp x 64 words
    const int akp = tid >> 4, am4 = (tid & 15) * 4;
    const uint32_t adst = (uint32_t)(akp * PAO + am4) * 4;
    const uint32_t* aS = g_atth + m0 + (size_t)akp * MTOT + am4;
    // B staging: 4 cpa16 per thread, kp = (tid>>6) + 4j, c4 = (tid&63)*4
    const int bkp = tid >> 6, bc4 = (tid & 63) * 4;
    const uint32_t bdst = (uint32_t)(bkp * PBO + bc4) * 4;
    const uint32_t* bS = g_woh + n0 + (size_t)bkp * DOUT + bc4;

    const uint32_t aA[2] = {sbase, sbase + AOSZ * 4};
    const uint32_t bA[2] = {sbase + 2 * AOSZ * 4, sbase + (2 * AOSZ + BOSZ) * 4};

#define O_ISSUE(buf, k0p)                                                     \
    {                                                                         \
        cpa16(aA[buf] + adst, aS + (size_t)(k0p) * MTOT);                     \
        _Pragma("unroll") for (int j = 0; j < 4; j++)                         \
            cpa16(bA[buf] + bdst + j * (4 * PBO * 4),                         \
                  bS + (size_t)((k0p) + 4 * j) * DOUT);                       \
        CP_COMMIT();                                                          \
    }

    float acc[2][8][4];
#pragma unroll
    for (int i = 0; i < 2; i++)
#pragma unroll
        for (int j = 0; j < 8; j++)
#pragma unroll
            for (int r = 0; r < 4; r++) acc[i][j][r] = 0.f;

    const int NCH = (DQKV / 2) / BKP;   // 16 chunks
    O_ISSUE(0, 0);
    for (int cc = 0; cc < NCH; cc++) {
        const int cur = cc & 1;
        if (cc + 1 < NCH) { O_ISSUE(cur ^ 1, (cc + 1) * BKP); CP_WAIT(1); }
        else              { CP_WAIT(0); }
        __syncthreads();
        mma_chunk<PAO, PBO>(sm + cur * AOSZ, sm + 2 * AOSZ + cur * BOSZ,
                            acc, mw, nw, c, g);
        __syncthreads();
    }
#undef O_ISSUE

    // Epilogue: two 128-col halves through smem bounce [n][m] (fp32, pitch 68)
    float* ep = (float*)sm;   // 128*68*4 = 34816 B <= SMEM_O
#pragma unroll
    for (int h = 0; h < 2; h++) {
        if ((nw >> 7) == h) {
#pragma unroll
            for (int fm = 0; fm < 2; fm++)
#pragma unroll
                for (int fn = 0; fn < 8; fn++) {
                    int nrel = (nw & 127) + fn * 8 + c * 2;
                    int mrel = mw + fm * 16 + g;
                    ep[nrel * EPPO + mrel]           = acc[fm][fn][0];
                    ep[(nrel + 1) * EPPO + mrel]     = acc[fm][fn][1];
                    ep[nrel * EPPO + mrel + 8]       = acc[fm][fn][2];
                    ep[(nrel + 1) * EPPO + mrel + 8] = acc[fm][fn][3];
                }
        }
        __syncthreads();
#pragma unroll
        for (int i = 0; i < 8; i++) {
            int f = tid + i * 256;
            int nr = f >> 4;                // 0..127
            int m4 = (f & 15) * 4;          // 0..60
            float4 v = *(float4*)&ep[nr * EPPO + m4];
            float bj = __ldg(bo + n0 + h * 128 + nr);
            v.x += bj; v.y += bj; v.z += bj; v.w += bj;
            *(float4*)(out + ((size_t)(bb * DOUT + n0 + h * 128 + nr)) * LEN
                       + l0 + m4) = v;
        }
        __syncthreads();
    }
}

// ---------------- launch ----------------
extern "C" void kernel_launch(void* const* d_in, const int* in_sizes, int n_in,
                              void* d_out, int out_size)
{
    const float* x  = (const float*)d_in[0];
    const float* Wq = (const float*)d_in[1];
    const float* bq = (const float*)d_in[2];
    const float* Wk = (const float*)d_in[3];
    const float* bk = (const float*)d_in[4];
    const float* Wv = (const float*)d_in[5];
    const float* bv = (const float*)d_in[6];
    const float* Wo = (const float*)d_in[7];
    const float* bo = (const float*)d_in[8];
    float* out = (float*)d_out;

    cudaFuncSetAttribute(qkv_mma, cudaFuncAttributeMaxDynamicSharedMemorySize, SMEM_Q);
    cudaFuncSetAttribute(out_mma, cudaFuncAttributeMaxDynamicSharedMemorySize, SMEM_O);

    pack_all<<<(NTI + 255) / 256, 256>>>(x, Wq, Wk, Wv, Wo);
    qkv_mma<<<dim3(MTOT / BM, 12), 256, SMEM_Q>>>(bq, bk, bv);
    attn_t<<<BATCH * NHEAD * (LEN / 32), 256>>>();
    out_mma<<<dim3(MTOT / OM, DOUT / ON), 256, SMEM_O>>>(bo, out);
}

// round 12
// speedup vs baseline: 1.0794x; 1.0794x over previous
#include <cuda_runtime.h>
#include <cuda_fp16.h>
#include <cstdint>

// ---------------- problem constants ----------------
#define BATCH 8
#define NHID 256
#define LEN 2048
#define NHEAD 8
#define HDIM 64
#define DQKV 512
#define DOUT 2048
#define MTOT (BATCH * LEN)   // 16384

// ---------------- qkv GEMM tiling (fp16, k-pair packed) ----------------
#define BM 128
#define BN 128
#define BKP 16                // kp rows per chunk (= 32 k elements)
#define PQ 136                // smem pitch in uint32
#define QSZ (BKP * PQ)        // 2176 uint32 per buffer
#define NSTAGE 3
#define SMEM_Q (2 * NSTAGE * QSZ * 4)   // 52224 bytes

// ---------------- out GEMM tiling (128x128 CTA, 64x64 warp, 128 thr) ----------------
#define OM 128
#define ON 128
#define POB 136               // A and B smem pitch (uint32)
#define OBSZ (BKP * POB)      // 2176 uint32 per buffer
#define EPPO 132              // epilogue bounce pitch (m rows are 128 floats wide!)
#define SMEM_O (4 * OBSZ * 4)   // 34816 B (A0,A1,B0,B1); epilogue half = 64*132*4 = 33792 B

// Scratch (allocation-free). Operands packed as half2 k-pairs: word[kp][col].
__device__ uint32_t g_xh[(size_t)(BATCH * NHID / 2) * LEN];   // [1024][2048]
__device__ uint32_t g_wqh[(NHID / 2) * DQKV];
__device__ uint32_t g_wkh[(NHID / 2) * DQKV];
__device__ uint32_t g_wvh[(NHID / 2) * DQKV];
__device__ uint32_t g_woh[(DQKV / 2) * DOUT];                 // [256][2048]
__device__ uint32_t g_qkvh[(size_t)MTOT * 768];               // fp16 q/k/v, d-pair words
__device__ uint32_t g_atth[(size_t)(DQKV / 2) * MTOT];        // [256][16384]

// ---------------- helpers ----------------
__device__ __forceinline__ uint32_t pkh2(float a, float b) {
    __half2 h = __floats2half2_rn(a, b);
    return *reinterpret_cast<uint32_t*>(&h);
}
__device__ __forceinline__ float2 uph2(uint32_t u) {
    __half2 h;
    *reinterpret_cast<uint32_t*>(&h) = u;
    return __half22float2(h);
}
__device__ __forceinline__ uint32_t smem_u32(const void* p) {
    uint32_t a;
    asm("{ .reg .u64 t; cvta.to.shared.u64 t, %1; cvt.u32.u64 %0, t; }" : "=r"(a) : "l"(p));
    return a;
}
__device__ __forceinline__ void cpa16(uint32_t dst, const void* src) {
    asm volatile("cp.async.cg.shared.global [%0], [%1], 16;" :: "r"(dst), "l"(src));
}
#define CP_COMMIT() asm volatile("cp.async.commit_group;" ::: "memory")
#define CP_WAIT(n)  asm volatile("cp.async.wait_group %0;" :: "n"(n) : "memory")

__device__ __forceinline__ void mma16(float& d0, float& d1, float& d2, float& d3,
                                      uint32_t a0, uint32_t a1, uint32_t a2, uint32_t a3,
                                      uint32_t b0, uint32_t b1) {
    asm volatile(
        "mma.sync.aligned.m16n8k16.row.col.f32.f16.f16.f32 "
        "{%0,%1,%2,%3}, {%4,%5,%6,%7}, {%8,%9}, {%0,%1,%2,%3};"
        : "+f"(d0), "+f"(d1), "+f"(d2), "+f"(d3)
        : "r"(a0), "r"(a1), "r"(a2), "r"(a3), "r"(b0), "r"(b1));
}

// ---- 32x64 warp-tile chunk (qkv kernel) ----
template <int APITCH, int BPITCH>
__device__ __forceinline__ void mma_chunk(const uint32_t* __restrict__ Ab,
                                          const uint32_t* __restrict__ Bb,
                                          float acc[2][8][4], int mw, int nw,
                                          int c, int g) {
#pragma unroll
    for (int ks = 0; ks < 2; ks++) {
        const int kb = ks * 8;
        uint32_t a[2][4];
#pragma unroll
        for (int fm = 0; fm < 2; fm++) {
            const uint32_t* p = Ab + (kb + c) * APITCH + mw + fm * 16 + g;
            a[fm][0] = p[0];
            a[fm][1] = p[8];
            a[fm][2] = p[4 * APITCH];
            a[fm][3] = p[4 * APITCH + 8];
        }
#pragma unroll
        for (int fn = 0; fn < 8; fn++) {
            const uint32_t* q = Bb + (kb + c) * BPITCH + nw + fn * 8 + g;
            uint32_t b0 = q[0];
            uint32_t b1 = q[4 * BPITCH];
            mma16(acc[0][fn][0], acc[0][fn][1], acc[0][fn][2], acc[0][fn][3],
                  a[0][0], a[0][1], a[0][2], a[0][3], b0, b1);
            mma16(acc[1][fn][0], acc[1][fn][1], acc[1][fn][2], acc[1][fn][3],
                  a[1][0], a[1][1], a[1][2], a[1][3], b0, b1);
        }
    }
}

// ---- 64x64 warp-tile chunk (out kernel): 32 HMMA per 4KB of fragments ----
__device__ __forceinline__ void mma_chunk64(const uint32_t* __restrict__ Ab,
                                            const uint32_t* __restrict__ Bb,
                                            float acc[4][8][4], int mw, int nw,
                                            int c, int g) {
#pragma unroll
    for (int ks = 0; ks < 2; ks++) {
        const int kb = ks * 8;
        uint32_t a[4][4];
#pragma unroll
        for (int fm = 0; fm < 4; fm++) {
            const uint32_t* p = Ab + (kb + c) * POB + mw + fm * 16 + g;
            a[fm][0] = p[0];
            a[fm][1] = p[8];
            a[fm][2] = p[4 * POB];
            a[fm][3] = p[4 * POB + 8];
        }
#pragma unroll
        for (int fn = 0; fn < 8; fn++) {
            const uint32_t* q = Bb + (kb + c) * POB + nw + fn * 8 + g;
            uint32_t b0 = q[0];
            uint32_t b1 = q[4 * POB];
#pragma unroll
            for (int fm = 0; fm < 4; fm++)
                mma16(acc[fm][fn][0], acc[fm][fn][1], acc[fm][fn][2], acc[fm][fn][3],
                      a[fm][0], a[fm][1], a[fm][2], a[fm][3], b0, b1);
        }
    }
}

// ---------------- prep: pack fp32 [K][N] -> half2-k-pair words [K/2][N] ----------------
__device__ __forceinline__ void pack_item(const float* __restrict__ src,
                                          uint32_t* __restrict__ dst,
                                          int cols, int i) {
    int kp = i / (cols / 4);
    int c4 = (i % (cols / 4)) * 4;
    const float4 r0 = *(const float4*)(src + (size_t)(2 * kp) * cols + c4);
    const float4 r1 = *(const float4*)(src + (size_t)(2 * kp + 1) * cols + c4);
    uint4 o;
    o.x = pkh2(r0.x, r1.x);
    o.y = pkh2(r0.y, r1.y);
    o.z = pkh2(r0.z, r1.z);
    o.w = pkh2(r0.w, r1.w);
    *(uint4*)(dst + (size_t)kp * cols + c4) = o;
}

#define NXI ((BATCH * NHID / 2) * (LEN / 4))   // 524288
#define NWI ((NHID / 2) * (DQKV / 4))          // 16384
#define NOI ((DQKV / 2) * (DOUT / 4))          // 131072
#define NTI (NXI + 3 * NWI + NOI)              // 704512

__global__ __launch_bounds__(256) void pack_all(
    const float* __restrict__ x,  const float* __restrict__ wq,
    const float* __restrict__ wk, const float* __restrict__ wv,
    const float* __restrict__ wo)
{
    int i = blockIdx.x * 256 + threadIdx.x;
    if (i >= NTI) return;
    if (i < NXI)                { pack_item(x,  g_xh,  LEN,  i); }
    else if (i < NXI + NWI)     { pack_item(wq, g_wqh, DQKV, i - NXI); }
    else if (i < NXI + 2 * NWI) { pack_item(wk, g_wkh, DQKV, i - NXI - NWI); }
    else if (i < NXI + 3 * NWI) { pack_item(wv, g_wvh, DQKV, i - NXI - 2 * NWI); }
    else                        { pack_item(wo, g_woh, DOUT, i - NXI - 3 * NWI); }
}

// ---------------- Kernel 1: QKV projection (unchanged from R9) ----------------
__global__ __launch_bounds__(256, 2) void qkv_mma(
    const float* __restrict__ bq, const float* __restrict__ bk,
    const float* __restrict__ bv)
{
    extern __shared__ uint32_t sm[];
    const int tid = threadIdx.x, lane = tid & 31, wid = tid >> 5;
    const int c = lane & 3, g = lane >> 2;
    const int mw = (wid & 3) * 32, nw = (wid >> 2) * 64;

    const int m0 = blockIdx.x * BM;
    const int bb = m0 >> 11;
    const int l0 = m0 & (LEN - 1);
    const int yy = blockIdx.y;               // 0..11
    const int mat = yy >> 2;
    const int n0 = (yy & 3) * BN;

    const uint32_t* W = (mat == 0) ? g_wqh : (mat == 1) ? g_wkh : g_wvh;
    const float* bias = (mat == 0) ? bq : (mat == 1) ? bk : bv;

    const int fkp0 = tid >> 5;
    const uint32_t sbase = smem_u32(sm);
    uint32_t aAddr[NSTAGE], bAddr[NSTAGE];
#pragma unroll
    for (int i = 0; i < NSTAGE; i++) {
        aAddr[i] = sbase + i * QSZ * 4;
        bAddr[i] = sbase + (NSTAGE + i) * QSZ * 4;
    }
    const int m4s = (tid & 31) * 4;
    const uint32_t sdst = (uint32_t)(fkp0 * PQ + m4s) * 4;
    const uint32_t* aS = g_xh + ((size_t)bb * 128 + fkp0) * LEN + l0 + m4s;
    const uint32_t* bS = W + (size_t)fkp0 * DQKV + n0 + m4s;

#define Q_ISSUE(buf, k0p)                                                     \
    {                                                                         \
        _Pragma("unroll") for (int j = 0; j < 2; j++) {                       \
            cpa16(aAddr[buf] + sdst + j * (8 * PQ * 4),                       \
                  aS + (size_t)((k0p) + 8 * j) * LEN);                        \
            cpa16(bAddr[buf] + sdst + j * (8 * PQ * 4),                       \
                  bS + (size_t)((k0p) + 8 * j) * DQKV);                       \
        }                                                                     \
        CP_COMMIT();                                                          \
    }

    float acc[2][8][4];
#pragma unroll
    for (int i = 0; i < 2; i++)
#pragma unroll
        for (int j = 0; j < 8; j++)
#pragma unroll
            for (int r = 0; r < 4; r++) acc[i][j][r] = 0.f;

    const int NCH = (NHID / 2) / BKP;   // 8 chunks
    Q_ISSUE(0, 0);
    Q_ISSUE(1, BKP);
    for (int cc = 0; cc < NCH; cc++) {
        const int cur = cc % NSTAGE;
        if (cc == NCH - 1) { CP_WAIT(0); } else { CP_WAIT(1); }
        __syncthreads();
        if (cc + 2 < NCH) Q_ISSUE((cc + 2) % NSTAGE, (cc + 2) * BKP);
        mma_chunk<PQ, PQ>(sm + cur * QSZ, sm + (NSTAGE + cur) * QSZ,
                          acc, mw, nw, c, g);
    }
#undef Q_ISSUE

    // Epilogue: bias + pack to fp16 d-pair words -> g_qkvh
#pragma unroll
    for (int fm = 0; fm < 2; fm++)
#pragma unroll
        for (int fn = 0; fn < 8; fn++) {
            int m = m0 + mw + fm * 16 + g;
            int n = nw + fn * 8 + c * 2;
            float bx = __ldg(bias + n0 + n), by = __ldg(bias + n0 + n + 1);
            uint32_t* p = g_qkvh + (size_t)m * 768 + mat * 256 + ((n0 + n) >> 1);
            p[0]               = pkh2(acc[fm][fn][0] + bx, acc[fm][fn][1] + by);
            p[(size_t)8 * 768] = pkh2(acc[fm][fn][2] + bx, acc[fm][fn][3] + by);
        }
}

// ---------------- Kernel 2: window-3 attention (unchanged from R9) ----------------
__global__ __launch_bounds__(256) void attn_t()
{
    __shared__ float att_s[32 * 66];   // [li][d] pitch 66
    const int tid = threadIdx.x, warp = tid >> 5, lane = tid & 31;
    const int bid = blockIdx.x;
    const int b = bid >> 9;
    const int head = (bid >> 6) & 7;
    const int l0 = (bid & 63) * 32;

#pragma unroll
    for (int i = 0; i < 4; i++) {
        const int li = warp * 4 + i;
        const int l = l0 + li;
        const size_t mrow = (size_t)b * LEN + l;
        const uint32_t* base = g_qkvh + mrow * 768 + head * 32 + lane;
        const float2 qv = uph2(base[0]);

        float  s[3];
        float2 vv[3];
#pragma unroll
        for (int w = 0; w < 3; w++) {
            int lw = l + w - 1;
            bool ok = (unsigned)lw < (unsigned)LEN;
            float2 kv = make_float2(0.f, 0.f);
            vv[w] = make_float2(0.f, 0.f);
            if (ok) {
                const uint32_t* pw = base + (intptr_t)(w - 1) * 768;
                kv    = uph2(pw[256]);
                vv[w] = uph2(pw[512]);
            }
            float p = qv.x * kv.x + qv.y * kv.y;
            p += __shfl_xor_sync(0xffffffffu, p, 16);
            p += __shfl_xor_sync(0xffffffffu, p, 8);
            p += __shfl_xor_sync(0xffffffffu, p, 4);
            p += __shfl_xor_sync(0xffffffffu, p, 2);
            p += __shfl_xor_sync(0xffffffffu, p, 1);
            s[w] = p * 0.125f;
        }

        float mx = fmaxf(s[0], fmaxf(s[1], s[2]));
        float e0 = expf(s[0] - mx), e1 = expf(s[1] - mx), e2 = expf(s[2] - mx);
        float inv = 1.0f / (e0 + e1 + e2);
        float ax = (e0 * vv[0].x + e1 * vv[1].x + e2 * vv[2].x) * inv;
        float ay = (e0 * vv[0].y + e1 * vv[1].y + e2 * vv[2].y) * inv;
        *(float2*)&att_s[li * 66 + lane * 2] = make_float2(ax, ay);
    }
    __syncthreads();

    {
        int dp = tid >> 3;              // 0..31
        int l4 = (tid & 7) * 4;         // 0..28
        uint4 v;
        v.x = pkh2(att_s[(l4 + 0) * 66 + 2 * dp], att_s[(l4 + 0) * 66 + 2 * dp + 1]);
        v.y = pkh2(att_s[(l4 + 1) * 66 + 2 * dp], att_s[(l4 + 1) * 66 + 2 * dp + 1]);
        v.z = pkh2(att_s[(l4 + 2) * 66 + 2 * dp], att_s[(l4 + 2) * 66 + 2 * dp + 1]);
        v.w = pkh2(att_s[(l4 + 3) * 66 + 2 * dp], att_s[(l4 + 3) * 66 + 2 * dp + 1]);
        *(uint4*)(g_atth + (size_t)(head * 32 + dp) * MTOT
                  + (size_t)b * LEN + l0 + l4) = v;
    }
}

// ---------------- Kernel 3: output projection — 128x128 CTA, 64x64 warps ----------------
__global__ __launch_bounds__(128, 2) void out_mma(
    const float* __restrict__ bo, float* __restrict__ out)
{
    extern __shared__ uint32_t sm[];
    // layout: A0, A1, B0, B1 [OBSZ each]
    const int tid = threadIdx.x, lane = tid & 31, wid = tid >> 5;
    const int c = lane & 3, g = lane >> 2;
    const int mw = (wid & 1) * 64, nw = (wid >> 1) * 64;   // 2x2 warps of 64x64

    const int m0 = blockIdx.x * OM;        // 128-aligned, never crosses batch
    const int bb = m0 >> 11;
    const int l0 = m0 & (LEN - 1);
    const int n0 = blockIdx.y * ON;

    const uint32_t sbase = smem_u32(sm);
    // staging: j<4: kp = (tid>>5) + 4j, col4 = (tid&31)*4
    const int kk0 = tid >> 5, m4s = (tid & 31) * 4;
    const uint32_t sdst = (uint32_t)(kk0 * POB + m4s) * 4;
    const uint32_t* aS = g_atth + m0 + (size_t)kk0 * MTOT + m4s;
    const uint32_t* bS = g_woh + n0 + (size_t)kk0 * DOUT + m4s;

    const uint32_t aA[2] = {sbase, sbase + OBSZ * 4};
    const uint32_t bA[2] = {sbase + 2 * OBSZ * 4, sbase + 3 * OBSZ * 4};

#define O_ISSUE(buf, k0p)                                                     \
    {                                                                         \
        _Pragma("unroll") for (int j = 0; j < 4; j++) {                       \
            cpa16(aA[buf] + sdst + j * (4 * POB * 4),                         \
                  aS + (size_t)((k0p) + 4 * j) * MTOT);                       \
            cpa16(bA[buf] + sdst + j * (4 * POB * 4),                         \
                  bS + (size_t)((k0p) + 4 * j) * DOUT);                       \
        }                                                                     \
        CP_COMMIT();                                                          \
    }

    float acc[4][8][4];
#pragma unroll
    for (int i = 0; i < 4; i++)
#pragma unroll
        for (int j = 0; j < 8; j++)
#pragma unroll
            for (int r = 0; r < 4; r++) acc[i][j][r] = 0.f;

    const int NCH = (DQKV / 2) / BKP;   // 16 chunks
    O_ISSUE(0, 0);
    for (int cc = 0; cc < NCH; cc++) {
        const int cur = cc & 1;
        if (cc + 1 < NCH) { O_ISSUE(cur ^ 1, (cc + 1) * BKP); CP_WAIT(1); }
        else              { CP_WAIT(0); }
        __syncthreads();
        mma_chunk64(sm + cur * OBSZ, sm + (2 + cur) * OBSZ, acc, mw, nw, c, g);
        __syncthreads();
    }
#undef O_ISSUE

    // Epilogue: two 64-n halves through smem bounce [n][m] (fp32, pitch 132)
    float* ep = (float*)sm;   // 64*132*4 = 33792 B <= SMEM_O
#pragma unroll
    for (int h = 0; h < 2; h++) {
        if ((nw >> 6) == h) {
#pragma unroll
            for (int fm = 0; fm < 4; fm++)
#pragma unroll
                for (int fn = 0; fn < 8; fn++) {
                    int nrel = fn * 8 + c * 2;        // 0..63 within half
                    int mrel = mw + fm * 16 + g;      // 0..127
                    ep[nrel * EPPO + mrel]           = acc[fm][fn][0];
                    ep[(nrel + 1) * EPPO + mrel]     = acc[fm][fn][1];
                    ep[nrel * EPPO + mrel + 8]       = acc[fm][fn][2];
                    ep[(nrel + 1) * EPPO + mrel + 8] = acc[fm][fn][3];
                }
        }
        __syncthreads();
#pragma unroll
        for (int i = 0; i < 16; i++) {
            int f = tid + i * 128;
            int nr = f >> 5;                // 0..63
            int m4 = (f & 31) * 4;          // 0..124
            float4 v = *(float4*)&ep[nr * EPPO + m4];
            float bj = __ldg(bo + n0 + h * 64 + nr);
            v.x += bj; v.y += bj; v.z += bj; v.w += bj;
            *(float4*)(out + ((size_t)(bb * DOUT + n0 + h * 64 + nr)) * LEN
                       + l0 + m4) = v;
        }
        __syncthreads();
    }
}

// ---------------- launch ----------------
extern "C" void kernel_launch(void* const* d_in, const int* in_sizes, int n_in,
                              void* d_out, int out_size)
{
    const float* x  = (const float*)d_in[0];
    const float* Wq = (const float*)d_in[1];
    const float* bq = (const float*)d_in[2];
    const float* Wk = (const float*)d_in[3];
    const float* bk = (const float*)d_in[4];
    const float* Wv = (const float*)d_in[5];
    const float* bv = (const float*)d_in[6];
    const float* Wo = (const float*)d_in[7];
    const float* bo = (const float*)d_in[8];
    float* out = (float*)d_out;

    cudaFuncSetAttribute(qkv_mma, cudaFuncAttributeMaxDynamicSharedMemorySize, SMEM_Q);
    cudaFuncSetAttribute(out_mma, cudaFuncAttributeMaxDynamicSharedMemorySize, SMEM_O);

    pack_all<<<(NTI + 255) / 256, 256>>>(x, Wq, Wk, Wv, Wo);
    qkv_mma<<<dim3(MTOT / BM, 12), 256, SMEM_Q>>>(bq, bk, bv);
    attn_t<<<BATCH * NHEAD * (LEN / 32), 256>>>();
    out_mma<<<dim3(MTOT / OM, DOUT / ON), 128, SMEM_O>>>(bo, out);
}

// round 13
// speedup vs baseline: 1.1196x; 1.0372x over previous
#include <cuda_runtime.h>
#include <cuda_fp16.h>
#include <cstdint>

// ---------------- problem constants ----------------
#define BATCH 8
#define NHID 256
#define LEN 2048
#define NHEAD 8
#define HDIM 64
#define DQKV 512
#define DOUT 2048
#define MTOT (BATCH * LEN)   // 16384

// ---------------- shared GEMM tiling (128x128 CTA, 64x64 warp, 128 thr) ----------------
#define BKP 16                // kp rows per chunk (= 32 k elements)
#define POB 136               // smem pitch (uint32)
#define OBSZ (BKP * POB)      // 2176 uint32 per buffer
#define EPPO 132              // out epilogue bounce pitch
#define SMEM_G (4 * OBSZ * 4)   // 34816 B (A0,A1,B0,B1); out epi half = 64*132*4 = 33792 B

// Scratch (allocation-free). Operands packed as half2 k-pairs: word[kp][col].
__device__ uint32_t g_xh[(size_t)(BATCH * NHID / 2) * LEN];   // [1024][2048]
__device__ uint32_t g_wqh[(NHID / 2) * DQKV];
__device__ uint32_t g_wkh[(NHID / 2) * DQKV];
__device__ uint32_t g_wvh[(NHID / 2) * DQKV];
__device__ uint32_t g_woh[(DQKV / 2) * DOUT];                 // [256][2048]
__device__ uint32_t g_qkvh[(size_t)MTOT * 768];               // fp16 q/k/v, d-pair words
__device__ uint32_t g_atth[(size_t)(DQKV / 2) * MTOT];        // [256][16384]

// ---------------- helpers ----------------
__device__ __forceinline__ uint32_t pkh2(float a, float b) {
    __half2 h = __floats2half2_rn(a, b);
    return *reinterpret_cast<uint32_t*>(&h);
}
__device__ __forceinline__ float2 uph2(uint32_t u) {
    __half2 h;
    *reinterpret_cast<uint32_t*>(&h) = u;
    return __half22float2(h);
}
__device__ __forceinline__ uint32_t smem_u32(const void* p) {
    uint32_t a;
    asm("{ .reg .u64 t; cvta.to.shared.u64 t, %1; cvt.u32.u64 %0, t; }" : "=r"(a) : "l"(p));
    return a;
}
__device__ __forceinline__ void cpa16(uint32_t dst, const void* src) {
    asm volatile("cp.async.cg.shared.global [%0], [%1], 16;" :: "r"(dst), "l"(src));
}
#define CP_COMMIT() asm volatile("cp.async.commit_group;" ::: "memory")
#define CP_WAIT(n)  asm volatile("cp.async.wait_group %0;" :: "n"(n) : "memory")

__device__ __forceinline__ void mma16(float& d0, float& d1, float& d2, float& d3,
                                      uint32_t a0, uint32_t a1, uint32_t a2, uint32_t a3,
                                      uint32_t b0, uint32_t b1) {
    asm volatile(
        "mma.sync.aligned.m16n8k16.row.col.f32.f16.f16.f32 "
        "{%0,%1,%2,%3}, {%4,%5,%6,%7}, {%8,%9}, {%0,%1,%2,%3};"
        : "+f"(d0), "+f"(d1), "+f"(d2), "+f"(d3)
        : "r"(a0), "r"(a1), "r"(a2), "r"(a3), "r"(b0), "r"(b1));
}

// ---- 64x64 warp-tile chunk: 64 HMMA per 8KB of fragments (128 B/HMMA) ----
__device__ __forceinline__ void mma_chunk64(const uint32_t* __restrict__ Ab,
                                            const uint32_t* __restrict__ Bb,
                                            float acc[4][8][4], int mw, int nw,
                                            int c, int g) {
#pragma unroll
    for (int ks = 0; ks < 2; ks++) {
        const int kb = ks * 8;
        uint32_t a[4][4];
#pragma unroll
        for (int fm = 0; fm < 4; fm++) {
            const uint32_t* p = Ab + (kb + c) * POB + mw + fm * 16 + g;
            a[fm][0] = p[0];
            a[fm][1] = p[8];
            a[fm][2] = p[4 * POB];
            a[fm][3] = p[4 * POB + 8];
        }
#pragma unroll
        for (int fn = 0; fn < 8; fn++) {
            const uint32_t* q = Bb + (kb + c) * POB + nw + fn * 8 + g;
            uint32_t b0 = q[0];
            uint32_t b1 = q[4 * POB];
#pragma unroll
            for (int fm = 0; fm < 4; fm++)
                mma16(acc[fm][fn][0], acc[fm][fn][1], acc[fm][fn][2], acc[fm][fn][3],
                      a[fm][0], a[fm][1], a[fm][2], a[fm][3], b0, b1);
        }
    }
}

// ---------------- prep: pack fp32 [K][N] -> half2-k-pair words [K/2][N] ----------------
__device__ __forceinline__ void pack_item(const float* __restrict__ src,
                                          uint32_t* __restrict__ dst,
                                          int cols, int i) {
    int kp = i / (cols / 4);
    int c4 = (i % (cols / 4)) * 4;
    const float4 r0 = *(const float4*)(src + (size_t)(2 * kp) * cols + c4);
    const float4 r1 = *(const float4*)(src + (size_t)(2 * kp + 1) * cols + c4);
    uint4 o;
    o.x = pkh2(r0.x, r1.x);
    o.y = pkh2(r0.y, r1.y);
    o.z = pkh2(r0.z, r1.z);
    o.w = pkh2(r0.w, r1.w);
    *(uint4*)(dst + (size_t)kp * cols + c4) = o;
}

#define NXI ((BATCH * NHID / 2) * (LEN / 4))   // 524288
#define NWI ((NHID / 2) * (DQKV / 4))          // 16384
#define NOI ((DQKV / 2) * (DOUT / 4))          // 131072
#define NTI (NXI + 3 * NWI + NOI)              // 704512

__global__ __launch_bounds__(256) void pack_all(
    const float* __restrict__ x,  const float* __restrict__ wq,
    const float* __restrict__ wk, const float* __restrict__ wv,
    const float* __restrict__ wo)
{
    int i = blockIdx.x * 256 + threadIdx.x;
    if (i >= NTI) return;
    if (i < NXI)                { pack_item(x,  g_xh,  LEN,  i); }
    else if (i < NXI + NWI)     { pack_item(wq, g_wqh, DQKV, i - NXI); }
    else if (i < NXI + 2 * NWI) { pack_item(wk, g_wkh, DQKV, i - NXI - NWI); }
    else if (i < NXI + 3 * NWI) { pack_item(wv, g_wvh, DQKV, i - NXI - 2 * NWI); }
    else                        { pack_item(wo, g_woh, DOUT, i - NXI - 3 * NWI); }
}

// ---------------- Kernel 1: QKV projection — 128x128 CTA, 64x64 warps ----------------
__global__ __launch_bounds__(128, 2) void qkv_mma(
    const float* __restrict__ bq, const float* __restrict__ bk,
    const float* __restrict__ bv)
{
    extern __shared__ uint32_t sm[];
    // layout: A0, A1, B0, B1 [OBSZ each]
    const int tid = threadIdx.x, lane = tid & 31, wid = tid >> 5;
    const int c = lane & 3, g = lane >> 2;
    const int mw = (wid & 1) * 64, nw = (wid >> 1) * 64;   // 2x2 warps of 64x64

    const int m0 = blockIdx.x * 128;
    const int bb = m0 >> 11;
    const int l0 = m0 & (LEN - 1);
    const int yy = blockIdx.y;               // 0..11
    const int mat = yy >> 2;
    const int n0 = (yy & 3) * 128;

    const uint32_t* W = (mat == 0) ? g_wqh : (mat == 1) ? g_wkh : g_wvh;
    const float* bias = (mat == 0) ? bq : (mat == 1) ? bk : bv;

    const uint32_t sbase = smem_u32(sm);
    // staging: j<4: kp = (tid>>5) + 4j, col4 = (tid&31)*4
    const int kk0 = tid >> 5, m4s = (tid & 31) * 4;
    const uint32_t sdst = (uint32_t)(kk0 * POB + m4s) * 4;
    const uint32_t* aS = g_xh + ((size_t)bb * 128 + kk0) * LEN + l0 + m4s;
    const uint32_t* bS = W + (size_t)kk0 * DQKV + n0 + m4s;

    const uint32_t aA[2] = {sbase, sbase + OBSZ * 4};
    const uint32_t bA[2] = {sbase + 2 * OBSZ * 4, sbase + 3 * OBSZ * 4};

#define Q_ISSUE(buf, k0p)                                                     \
    {                                                                         \
        _Pragma("unroll") for (int j = 0; j < 4; j++) {                       \
            cpa16(aA[buf] + sdst + j * (4 * POB * 4),                         \
                  aS + (size_t)((k0p) + 4 * j) * LEN);                        \
            cpa16(bA[buf] + sdst + j * (4 * POB * 4),                         \
                  bS + (size_t)((k0p) + 4 * j) * DQKV);                       \
        }                                                                     \
        CP_COMMIT();                                                          \
    }

    float acc[4][8][4];
#pragma unroll
    for (int i = 0; i < 4; i++)
#pragma unroll
        for (int j = 0; j < 8; j++)
#pragma unroll
            for (int r = 0; r < 4; r++) acc[i][j][r] = 0.f;

    const int NCH = (NHID / 2) / BKP;   // 8 chunks
    Q_ISSUE(0, 0);
    for (int cc = 0; cc < NCH; cc++) {
        const int cur = cc & 1;
        if (cc + 1 < NCH) { Q_ISSUE(cur ^ 1, (cc + 1) * BKP); CP_WAIT(1); }
        else              { CP_WAIT(0); }
        __syncthreads();
        mma_chunk64(sm + cur * OBSZ, sm + (2 + cur) * OBSZ, acc, mw, nw, c, g);
        __syncthreads();
    }
#undef Q_ISSUE

    // Epilogue: bias + pack to fp16 d-pair words -> g_qkvh
#pragma unroll
    for (int fm = 0; fm < 4; fm++)
#pragma unroll
        for (int fn = 0; fn < 8; fn++) {
            int m = m0 + mw + fm * 16 + g;
            int n = nw + fn * 8 + c * 2;
            float bx = __ldg(bias + n0 + n), by = __ldg(bias + n0 + n + 1);
            uint32_t* p = g_qkvh + (size_t)m * 768 + mat * 256 + ((n0 + n) >> 1);
            p[0]               = pkh2(acc[fm][fn][0] + bx, acc[fm][fn][1] + by);
            p[(size_t)8 * 768] = pkh2(acc[fm][fn][2] + bx, acc[fm][fn][3] + by);
        }
}

// ---------------- Kernel 2: window-3 attention (unchanged from R12) ----------------
__global__ __launch_bounds__(256) void attn_t()
{
    __shared__ float att_s[32 * 66];   // [li][d] pitch 66
    const int tid = threadIdx.x, warp = tid >> 5, lane = tid & 31;
    const int bid = blockIdx.x;
    const int b = bid >> 9;
    const int head = (bid >> 6) & 7;
    const int l0 = (bid & 63) * 32;

#pragma unroll
    for (int i = 0; i < 4; i++) {
        const int li = warp * 4 + i;
        const int l = l0 + li;
        const size_t mrow = (size_t)b * LEN + l;
        const uint32_t* base = g_qkvh + mrow * 768 + head * 32 + lane;
        const float2 qv = uph2(base[0]);

        float  s[3];
        float2 vv[3];
#pragma unroll
        for (int w = 0; w < 3; w++) {
            int lw = l + w - 1;
            bool ok = (unsigned)lw < (unsigned)LEN;
            float2 kv = make_float2(0.f, 0.f);
            vv[w] = make_float2(0.f, 0.f);
            if (ok) {
                const uint32_t* pw = base + (intptr_t)(w - 1) * 768;
                kv    = uph2(pw[256]);
                vv[w] = uph2(pw[512]);
            }
            float p = qv.x * kv.x + qv.y * kv.y;
            p += __shfl_xor_sync(0xffffffffu, p, 16);
            p += __shfl_xor_sync(0xffffffffu, p, 8);
            p += __shfl_xor_sync(0xffffffffu, p, 4);
            p += __shfl_xor_sync(0xffffffffu, p, 2);
            p += __shfl_xor_sync(0xffffffffu, p, 1);
            s[w] = p * 0.125f;
        }

        float mx = fmaxf(s[0], fmaxf(s[1], s[2]));
        float e0 = expf(s[0] - mx), e1 = expf(s[1] - mx), e2 = expf(s[2] - mx);
        float inv = 1.0f / (e0 + e1 + e2);
        float ax = (e0 * vv[0].x + e1 * vv[1].x + e2 * vv[2].x) * inv;
        float ay = (e0 * vv[0].y + e1 * vv[1].y + e2 * vv[2].y) * inv;
        *(float2*)&att_s[li * 66 + lane * 2] = make_float2(ax, ay);
    }
    __syncthreads();

    {
        int dp = tid >> 3;              // 0..31
        int l4 = (tid & 7) * 4;         // 0..28
        uint4 v;
        v.x = pkh2(att_s[(l4 + 0) * 66 + 2 * dp], att_s[(l4 + 0) * 66 + 2 * dp + 1]);
        v.y = pkh2(att_s[(l4 + 1) * 66 + 2 * dp], att_s[(l4 + 1) * 66 + 2 * dp + 1]);
        v.z = pkh2(att_s[(l4 + 2) * 66 + 2 * dp], att_s[(l4 + 2) * 66 + 2 * dp + 1]);
        v.w = pkh2(att_s[(l4 + 3) * 66 + 2 * dp], att_s[(l4 + 3) * 66 + 2 * dp + 1]);
        *(uint4*)(g_atth + (size_t)(head * 32 + dp) * MTOT
                  + (size_t)b * LEN + l0 + l4) = v;
    }
}

// ---------------- Kernel 3: output projection (unchanged from R12) ----------------
__global__ __launch_bounds__(128, 2) void out_mma(
    const float* __restrict__ bo, float* __restrict__ out)
{
    extern __shared__ uint32_t sm[];
    const int tid = threadIdx.x, lane = tid & 31, wid = tid >> 5;
    const int c = lane & 3, g = lane >> 2;
    const int mw = (wid & 1) * 64, nw = (wid >> 1) * 64;

    const int m0 = blockIdx.x * 128;
    const int bb = m0 >> 11;
    const int l0 = m0 & (LEN - 1);
    const int n0 = blockIdx.y * 128;

    const uint32_t sbase = smem_u32(sm);
    const int kk0 = tid >> 5, m4s = (tid & 31) * 4;
    const uint32_t sdst = (uint32_t)(kk0 * POB + m4s) * 4;
    const uint32_t* aS = g_atth + m0 + (size_t)kk0 * MTOT + m4s;
    const uint32_t* bS = g_woh + n0 + (size_t)kk0 * DOUT + m4s;

    const uint32_t aA[2] = {sbase, sbase + OBSZ * 4};
    const uint32_t bA[2] = {sbase + 2 * OBSZ * 4, sbase + 3 * OBSZ * 4};

#define O_ISSUE(buf, k0p)                                                     \
    {                                                                         \
        _Pragma("unroll") for (int j = 0; j < 4; j++) {                       \
            cpa16(aA[buf] + sdst + j * (4 * POB * 4),                         \
                  aS + (size_t)((k0p) + 4 * j) * MTOT);                       \
            cpa16(bA[buf] + sdst + j * (4 * POB * 4),                         \
                  bS + (size_t)((k0p) + 4 * j) * DOUT);                       \
        }                                                                     \
        CP_COMMIT();                                                          \
    }

    float acc[4][8][4];
#pragma unroll
    for (int i = 0; i < 4; i++)
#pragma unroll
        for (int j = 0; j < 8; j++)
#pragma unroll
            for (int r = 0; r < 4; r++) acc[i][j][r] = 0.f;

    const int NCH = (DQKV / 2) / BKP;   // 16 chunks
    O_ISSUE(0, 0);
    for (int cc = 0; cc < NCH; cc++) {
        const int cur = cc & 1;
        if (cc + 1 < NCH) { O_ISSUE(cur ^ 1, (cc + 1) * BKP); CP_WAIT(1); }
        else              { CP_WAIT(0); }
        __syncthreads();
        mma_chunk64(sm + cur * OBSZ, sm + (2 + cur) * OBSZ, acc, mw, nw, c, g);
        __syncthreads();
    }
#undef O_ISSUE

    // Epilogue: two 64-n halves through smem bounce [n][m] (fp32, pitch 132)
    float* ep = (float*)sm;   // 64*132*4 = 33792 B <= SMEM_G
#pragma unroll
    for (int h = 0; h < 2; h++) {
        if ((nw >> 6) == h) {
#pragma unroll
            for (int fm = 0; fm < 4; fm++)
#pragma unroll
                for (int fn = 0; fn < 8; fn++) {
                    int nrel = fn * 8 + c * 2;
                    int mrel = mw + fm * 16 + g;
                    ep[nrel * EPPO + mrel]           = acc[fm][fn][0];
                    ep[(nrel + 1) * EPPO + mrel]     = acc[fm][fn][1];
                    ep[nrel * EPPO + mrel + 8]       = acc[fm][fn][2];
                    ep[(nrel + 1) * EPPO + mrel + 8] = acc[fm][fn][3];
                }
        }
        __syncthreads();
#pragma unroll
        for (int i = 0; i < 16; i++) {
            int f = tid + i * 128;
            int nr = f >> 5;
            int m4 = (f & 31) * 4;
            float4 v = *(float4*)&ep[nr * EPPO + m4];
            float bj = __ldg(bo + n0 + h * 64 + nr);
            v.x += bj; v.y += bj; v.z += bj; v.w += bj;
            *(float4*)(out + ((size_t)(bb * DOUT + n0 + h * 64 + nr)) * LEN
                       + l0 + m4) = v;
        }
        __syncthreads();
    }
}

// ---------------- launch ----------------
extern "C" void kernel_launch(void* const* d_in, const int* in_sizes, int n_in,
                              void* d_out, int out_size)
{
    const float* x  = (const float*)d_in[0];
    const float* Wq = (const float*)d_in[1];
    const float* bq = (const float*)d_in[2];
    const float* Wk = (const float*)d_in[3];
    const float* bk = (const float*)d_in[4];
    const float* Wv = (const float*)d_in[5];
    const float* bv = (const float*)d_in[6];
    const float* Wo = (const float*)d_in[7];
    const float* bo = (const float*)d_in[8];
    float* out = (float*)d_out;

    cudaFuncSetAttribute(qkv_mma, cudaFuncAttributeMaxDynamicSharedMemorySize, SMEM_G);
    cudaFuncSetAttribute(out_mma, cudaFuncAttributeMaxDynamicSharedMemorySize, SMEM_G);

    pack_all<<<(NTI + 255) / 256, 256>>>(x, Wq, Wk, Wv, Wo);
    qkv_mma<<<dim3(MTOT / 128, 12), 128, SMEM_G>>>(bq, bk, bv);
    attn_t<<<BATCH * NHEAD * (LEN / 32), 256>>>();
    out_mma<<<dim3(MTOT / 128, DOUT / 128), 128, SMEM_G>>>(bo, out);
}